// round 1
// baseline (speedup 1.0000x reference)
#include <cuda_runtime.h>
#include <math.h>

// ---------------------------------------------------------------------------
// Gemma3 prefill forward, fp32 SIMT baseline.
// L=12, D=1152, NH=4 (NG=1), HD=256, F=6912, V=32768, B=1, T=128, C=1920,
// S=2048, CAP=50, scale=1/16.
// Output layout assumed: [logits (128*32768)] [k_slices (12*128*256)]
// [v_slices (12*256*128)], all fp32.
// ---------------------------------------------------------------------------

#define LAY   12
#define DMODEL 1152
#define NHEAD 4
#define HDIM  256
#define FFDIM 6912
#define VOCAB 32768
#define TTOK  128
#define CCTX  1920
#define STOT  2048
#define QKVW  1536   // (NH+2)*HD

// ---- scratch (single device global, no allocations) ----
// offsets (floats)
#define OFF_H     0                       // 128*1152
#define OFF_X     (OFF_H + TTOK*DMODEL)   // 128*1152
#define OFF_QKV   (OFF_X + TTOK*DMODEL)   // 128*1536
#define OFF_Q     (OFF_QKV + TTOK*QKVW)   // 4*128*256
#define OFF_K     (OFF_Q + NHEAD*TTOK*HDIM)      // 2048*256
#define OFF_V     (OFF_K + STOT*HDIM)            // 256*2048
#define OFF_SC    (OFF_V + HDIM*STOT)            // 4*128*2048
#define OFF_ATT   (OFF_SC + NHEAD*TTOK*STOT)     // 128*1024
#define OFF_PROJ  (OFF_ATT + TTOK*NHEAD*HDIM)    // 128*1152
#define OFF_FF1   (OFF_PROJ + TTOK*DMODEL)       // 128*6912
#define OFF_FF2   (OFF_FF1 + TTOK*FFDIM)         // 128*6912
#define SCRATCH_TOTAL (OFF_FF2 + TTOK*FFDIM)

__device__ float g_scratch[SCRATCH_TOTAL];

// ---------------------------------------------------------------------------
// Generic tiled GEMM kernels. M,N multiples of 64 (M=128 everywhere), K mult 16.
// 64x64 tile, 256 threads, 4x4 per thread.
// ---------------------------------------------------------------------------

__global__ __launch_bounds__(256) void gemm_nn(
    const float* __restrict__ A, const float* __restrict__ B, float* __restrict__ Cm,
    int M, int N, int K, int lda, int ldb, int ldc,
    long sA, long sB, long sC)
{
    int bz = blockIdx.z;
    A += (long)bz * sA; B += (long)bz * sB; Cm += (long)bz * sC;
    int bm = blockIdx.y * 64, bn = blockIdx.x * 64;

    __shared__ float As[16][64];
    __shared__ float Bs[16][64];

    int tid = threadIdx.x;
    int tx = tid & 15, ty = tid >> 4;
    float acc[4][4] = {};

    for (int k0 = 0; k0 < K; k0 += 16) {
        {
            int r = tid >> 2; int c = (tid & 3) * 4;
            float4 a = *(const float4*)(A + (long)(bm + r) * lda + k0 + c);
            As[c+0][r] = a.x; As[c+1][r] = a.y; As[c+2][r] = a.z; As[c+3][r] = a.w;
        }
        {
            int r = tid >> 4; int c = (tid & 15) * 4;
            float4 b = *(const float4*)(B + (long)(k0 + r) * ldb + bn + c);
            *(float4*)&Bs[r][c] = b;
        }
        __syncthreads();
        #pragma unroll
        for (int kk = 0; kk < 16; kk++) {
            float a0 = As[kk][ty*4+0], a1 = As[kk][ty*4+1],
                  a2 = As[kk][ty*4+2], a3 = As[kk][ty*4+3];
            float b0 = Bs[kk][tx*4+0], b1 = Bs[kk][tx*4+1],
                  b2 = Bs[kk][tx*4+2], b3 = Bs[kk][tx*4+3];
            acc[0][0] += a0*b0; acc[0][1] += a0*b1; acc[0][2] += a0*b2; acc[0][3] += a0*b3;
            acc[1][0] += a1*b0; acc[1][1] += a1*b1; acc[1][2] += a1*b2; acc[1][3] += a1*b3;
            acc[2][0] += a2*b0; acc[2][1] += a2*b1; acc[2][2] += a2*b2; acc[2][3] += a2*b3;
            acc[3][0] += a3*b0; acc[3][1] += a3*b1; acc[3][2] += a3*b2; acc[3][3] += a3*b3;
        }
        __syncthreads();
    }
    #pragma unroll
    for (int i = 0; i < 4; i++)
        #pragma unroll
        for (int j = 0; j < 4; j++)
            Cm[(long)(bm + ty*4 + i) * ldc + bn + tx*4 + j] = acc[i][j];
}

// C = A @ B^T. A: MxK row-major. B: NxK row-major.
__global__ __launch_bounds__(256) void gemm_nt(
    const float* __restrict__ A, const float* __restrict__ B, float* __restrict__ Cm,
    int M, int N, int K, int lda, int ldb, int ldc,
    long sA, long sB, long sC)
{
    int bz = blockIdx.z;
    A += (long)bz * sA; B += (long)bz * sB; Cm += (long)bz * sC;
    int bm = blockIdx.y * 64, bn = blockIdx.x * 64;

    __shared__ float As[16][64];
    __shared__ float Bs[16][64];

    int tid = threadIdx.x;
    int tx = tid & 15, ty = tid >> 4;
    float acc[4][4] = {};

    for (int k0 = 0; k0 < K; k0 += 16) {
        {
            int r = tid >> 2; int c = (tid & 3) * 4;
            float4 a = *(const float4*)(A + (long)(bm + r) * lda + k0 + c);
            As[c+0][r] = a.x; As[c+1][r] = a.y; As[c+2][r] = a.z; As[c+3][r] = a.w;
        }
        {
            int r = tid >> 2; int c = (tid & 3) * 4;   // r = n idx, c = k offset
            float4 b = *(const float4*)(B + (long)(bn + r) * ldb + k0 + c);
            Bs[c+0][r] = b.x; Bs[c+1][r] = b.y; Bs[c+2][r] = b.z; Bs[c+3][r] = b.w;
        }
        __syncthreads();
        #pragma unroll
        for (int kk = 0; kk < 16; kk++) {
            float a0 = As[kk][ty*4+0], a1 = As[kk][ty*4+1],
                  a2 = As[kk][ty*4+2], a3 = As[kk][ty*4+3];
            float b0 = Bs[kk][tx*4+0], b1 = Bs[kk][tx*4+1],
                  b2 = Bs[kk][tx*4+2], b3 = Bs[kk][tx*4+3];
            acc[0][0] += a0*b0; acc[0][1] += a0*b1; acc[0][2] += a0*b2; acc[0][3] += a0*b3;
            acc[1][0] += a1*b0; acc[1][1] += a1*b1; acc[1][2] += a1*b2; acc[1][3] += a1*b3;
            acc[2][0] += a2*b0; acc[2][1] += a2*b1; acc[2][2] += a2*b2; acc[2][3] += a2*b3;
            acc[3][0] += a3*b0; acc[3][1] += a3*b1; acc[3][2] += a3*b2; acc[3][3] += a3*b3;
        }
        __syncthreads();
    }
    #pragma unroll
    for (int i = 0; i < 4; i++)
        #pragma unroll
        for (int j = 0; j < 4; j++)
            Cm[(long)(bm + ty*4 + i) * ldc + bn + tx*4 + j] = acc[i][j];
}

// ---------------------------------------------------------------------------
// RMSNorm: y = x * rsqrt(mean(x^2)+eps) * (1+w).  One block per row.
// ---------------------------------------------------------------------------
__global__ __launch_bounds__(256) void rms_kernel(
    const float* __restrict__ x, const float* __restrict__ w,
    float* __restrict__ y, int ncols)
{
    int row = blockIdx.x;
    const float* xr = x + (long)row * ncols;
    __shared__ float red[256];
    int tid = threadIdx.x;
    float ss = 0.f;
    for (int c = tid; c < ncols; c += 256) { float v = xr[c]; ss += v*v; }
    red[tid] = ss; __syncthreads();
    for (int s = 128; s > 0; s >>= 1) { if (tid < s) red[tid] += red[tid+s]; __syncthreads(); }
    float inv = rsqrtf(red[0] / ncols + 1e-6f);
    for (int c = tid; c < ncols; c += 256)
        y[(long)row * ncols + c] = xr[c] * inv * (1.f + w[c]);
}

// h += rms(p, w)
__global__ __launch_bounds__(256) void add_rms_kernel(
    float* __restrict__ h, const float* __restrict__ p,
    const float* __restrict__ w, int ncols)
{
    int row = blockIdx.x;
    const float* pr = p + (long)row * ncols;
    __shared__ float red[256];
    int tid = threadIdx.x;
    float ss = 0.f;
    for (int c = tid; c < ncols; c += 256) { float v = pr[c]; ss += v*v; }
    red[tid] = ss; __syncthreads();
    for (int s = 128; s > 0; s >>= 1) { if (tid < s) red[tid] += red[tid+s]; __syncthreads(); }
    float inv = rsqrtf(red[0] / ncols + 1e-6f);
    for (int c = tid; c < ncols; c += 256)
        h[(long)row * ncols + c] += pr[c] * inv * (1.f + w[c]);
}

// ---------------------------------------------------------------------------
// Q/K rmsnorm + RoPE + V scatter. One block per token t, 256 threads (= HD).
// qkv row layout per token: [q0 q1 q2 q3 k v], each 256.
// Writes: q -> (h, t, d); k -> Kfull[1920+t] and k-slice out;
//         v -> Vfull[d][1920+t] and v-slice out (d-major).
// ---------------------------------------------------------------------------
__global__ __launch_bounds__(256) void qk_rope_kernel(
    const float* __restrict__ qkv,
    const float* __restrict__ qw, const float* __restrict__ kw,
    const float* __restrict__ cosp, const float* __restrict__ sinp,
    float* __restrict__ qout, float* __restrict__ Kfull, float* __restrict__ Vfull,
    float* __restrict__ kslice, float* __restrict__ vslice)
{
    int t = blockIdx.x;
    int d = threadIdx.x;
    __shared__ float red[256];
    __shared__ float buf[256];

    float cosv = cosp[t * HDIM + d];
    float sinv = sinp[t * HDIM + d];

    for (int hidx = 0; hidx < 5; hidx++) {
        float v = qkv[(long)t * QKVW + hidx * HDIM + d];
        red[d] = v * v; __syncthreads();
        for (int s = 128; s > 0; s >>= 1) { if (d < s) red[d] += red[d+s]; __syncthreads(); }
        float inv = rsqrtf(red[0] / HDIM + 1e-6f);
        const float* w = (hidx < 4) ? qw : kw;
        float xn = v * inv * (1.f + w[d]);
        buf[d] = xn; __syncthreads();
        float rot = (d < 128) ? -buf[d + 128] : buf[d - 128];
        float r = xn * cosv + rot * sinv;
        if (hidx < 4) {
            qout[(long)hidx * TTOK * HDIM + (long)t * HDIM + d] = r;
        } else {
            Kfull[(long)(CCTX + t) * HDIM + d] = r;
            kslice[(long)t * HDIM + d] = r;
        }
        __syncthreads();
    }
    // v
    float vv = qkv[(long)t * QKVW + 5 * HDIM + d];
    Vfull[(long)d * STOT + CCTX + t] = vv;
    vslice[(long)d * TTOK + t] = vv;
}

// copy kv_v[i] (256 x 1920) into Vfull (256 x 2048) left block
__global__ __launch_bounds__(256) void copy_v_kernel(
    const float* __restrict__ src, float* __restrict__ Vfull)
{
    int idx = blockIdx.x * 256 + threadIdx.x;
    if (idx < HDIM * CCTX) {
        int d = idx / CCTX, s = idx % CCTX;
        Vfull[(long)d * STOT + s] = src[idx];
    }
}

// ---------------------------------------------------------------------------
// softmax with tanh soft-cap and additive mask. block = (t, h), 256 threads.
// ---------------------------------------------------------------------------
__global__ __launch_bounds__(256) void softmax_kernel(
    float* __restrict__ sc, const float* __restrict__ mask)
{
    int t = blockIdx.x, h = blockIdx.y;
    float* row = sc + ((long)h * TTOK + t) * STOT;
    const float* mrow = mask + (long)t * STOT;
    __shared__ float red[256];
    int tid = threadIdx.x;
    const float scale = 0.0625f;          // 1/sqrt(256)
    const float invcap = 1.f / 50.f;

    float vals[8];
    float vmax = -1e30f;
    #pragma unroll
    for (int j = 0; j < 8; j++) {
        int s = tid + j * 256;
        float v = row[s] * scale;
        v = tanhf(v * invcap) * 50.f + mrow[s];
        vals[j] = v;
        vmax = fmaxf(vmax, v);
    }
    red[tid] = vmax; __syncthreads();
    for (int s = 128; s > 0; s >>= 1) { if (tid < s) red[tid] = fmaxf(red[tid], red[tid+s]); __syncthreads(); }
    float m = red[0]; __syncthreads();
    float lsum = 0.f;
    #pragma unroll
    for (int j = 0; j < 8; j++) { vals[j] = expf(vals[j] - m); lsum += vals[j]; }
    red[tid] = lsum; __syncthreads();
    for (int s = 128; s > 0; s >>= 1) { if (tid < s) red[tid] += red[tid+s]; __syncthreads(); }
    float inv = 1.f / red[0];
    #pragma unroll
    for (int j = 0; j < 8; j++) row[tid + j * 256] = vals[j] * inv;
}

// ---------------------------------------------------------------------------
// gelu(tanh approx)(g) * u  -> g
// ---------------------------------------------------------------------------
__global__ __launch_bounds__(256) void gelu_mul_kernel(
    float* __restrict__ g, const float* __restrict__ u, int n)
{
    int idx = blockIdx.x * 256 + threadIdx.x;
    if (idx < n) {
        float x = g[idx];
        float x3 = x * x * x;
        float ge = 0.5f * x * (1.f + tanhf(0.7978845608028654f * (x + 0.044715f * x3)));
        g[idx] = ge * u[idx];
    }
}

// ---------------------------------------------------------------------------
// launch
// ---------------------------------------------------------------------------
extern "C" void kernel_launch(void* const* d_in, const int* in_sizes, int n_in,
                              void* d_out, int out_size)
{
    (void)in_sizes; (void)n_in; (void)out_size;
    const float* emb        = (const float*)d_in[0];
    const float* mask_g     = (const float*)d_in[1];
    const float* mask_l     = (const float*)d_in[2];
    const float* pe_cos     = (const float*)d_in[3];
    const float* pe_sin     = (const float*)d_in[4];
    const float* pe_cos_loc = (const float*)d_in[5];
    const float* pe_sin_loc = (const float*)d_in[6];
    const float* kv_k       = (const float*)d_in[7];
    const float* kv_v       = (const float*)d_in[8];
    const float* pre_attn_w = (const float*)d_in[9];
    const float* q_norm_w   = (const float*)d_in[10];
    const float* k_norm_w   = (const float*)d_in[11];
    const float* post_attn_w= (const float*)d_in[12];
    const float* pre_ff_w   = (const float*)d_in[13];
    const float* post_ff_w  = (const float*)d_in[14];
    const float* final_w    = (const float*)d_in[15];
    const float* w_qkv      = (const float*)d_in[16];
    const float* w_out      = (const float*)d_in[17];
    const float* w_gate     = (const float*)d_in[18];
    const float* w_up       = (const float*)d_in[19];
    const float* w_down     = (const float*)d_in[20];
    const float* w_lm       = (const float*)d_in[21];

    float* out   = (float*)d_out;
    float* logits = out;                                   // 128*32768
    float* kout   = out + (long)TTOK * VOCAB;              // 12*128*256
    float* vout   = kout + (long)LAY * TTOK * HDIM;        // 12*256*128

    void* sp = nullptr;
    cudaGetSymbolAddress(&sp, g_scratch);
    float* S = (float*)sp;
    float* g_h    = S + OFF_H;
    float* g_x    = S + OFF_X;
    float* g_qkv  = S + OFF_QKV;
    float* g_q    = S + OFF_Q;
    float* g_K    = S + OFF_K;
    float* g_V    = S + OFF_V;
    float* g_sc   = S + OFF_SC;
    float* g_att  = S + OFF_ATT;
    float* g_proj = S + OFF_PROJ;
    float* g_ff1  = S + OFF_FF1;
    float* g_ff2  = S + OFF_FF2;

    // h = embeddings
    cudaMemcpyAsync(g_h, emb, (long)TTOK * DMODEL * sizeof(float),
                    cudaMemcpyDeviceToDevice);

    for (int i = 0; i < LAY; i++) {
        bool is_local = ((i + 1) % 6 == 0);
        const float* cosP = is_local ? pe_cos_loc : pe_cos;
        const float* sinP = is_local ? pe_sin_loc : pe_sin;
        const float* mask = is_local ? mask_l : mask_g;

        // x = rms(h, pre_attn_norm_w)
        rms_kernel<<<TTOK, 256>>>(g_h, pre_attn_w + (long)i * DMODEL, g_x, DMODEL);

        // qkv = x @ w_qkv[i]   (128 x 1152 @ 1152 x 1536)
        gemm_nn<<<dim3(QKVW/64, TTOK/64, 1), 256>>>(
            g_x, w_qkv + (long)i * DMODEL * QKVW, g_qkv,
            TTOK, QKVW, DMODEL, DMODEL, QKVW, QKVW, 0, 0, 0);

        // Kfull[0:1920] = kv_k[i]  (contiguous); Vfull[:, 0:1920] = kv_v[i]
        cudaMemcpyAsync(g_K, kv_k + (long)i * CCTX * HDIM,
                        (long)CCTX * HDIM * sizeof(float), cudaMemcpyDeviceToDevice);
        copy_v_kernel<<<(HDIM * CCTX + 255) / 256, 256>>>(
            kv_v + (long)i * HDIM * CCTX, g_V);

        // q/k norm + rope; fill last 128 rows of K / cols of V; emit slices
        qk_rope_kernel<<<TTOK, 256>>>(
            g_qkv, q_norm_w + (long)i * HDIM, k_norm_w + (long)i * HDIM,
            cosP, sinP, g_q, g_K, g_V,
            kout + (long)i * TTOK * HDIM, vout + (long)i * HDIM * TTOK);

        // scores[h] = q[h] @ K^T  (128 x 256 @ 256 x 2048), batched over heads
        gemm_nt<<<dim3(STOT/64, TTOK/64, NHEAD), 256>>>(
            g_q, g_K, g_sc,
            TTOK, STOT, HDIM, HDIM, HDIM, STOT,
            (long)TTOK * HDIM, 0, (long)TTOK * STOT);

        // softcap + mask + softmax
        softmax_kernel<<<dim3(TTOK, NHEAD), 256>>>(g_sc, mask);

        // out[h] = attn[h] @ V^T  (128 x 2048 @ 2048 x 256) -> cols h*256..
        gemm_nt<<<dim3(HDIM/64, TTOK/64, NHEAD), 256>>>(
            g_sc, g_V, g_att,
            TTOK, HDIM, STOT, STOT, STOT, NHEAD*HDIM,
            (long)TTOK * STOT, 0, (long)HDIM);

        // proj = att @ w_out[i]  (128 x 1024 @ 1024 x 1152)
        gemm_nn<<<dim3(DMODEL/64, TTOK/64, 1), 256>>>(
            g_att, w_out + (long)i * (NHEAD*HDIM) * DMODEL, g_proj,
            TTOK, DMODEL, NHEAD*HDIM, NHEAD*HDIM, DMODEL, DMODEL, 0, 0, 0);

        // h += rms(proj, post_attn_norm_w)
        add_rms_kernel<<<TTOK, 256>>>(g_h, g_proj, post_attn_w + (long)i * DMODEL, DMODEL);

        // fx = rms(h, pre_ff_norm_w)
        rms_kernel<<<TTOK, 256>>>(g_h, pre_ff_w + (long)i * DMODEL, g_x, DMODEL);

        // gate / up
        gemm_nn<<<dim3(FFDIM/64, TTOK/64, 1), 256>>>(
            g_x, w_gate + (long)i * DMODEL * FFDIM, g_ff1,
            TTOK, FFDIM, DMODEL, DMODEL, FFDIM, FFDIM, 0, 0, 0);
        gemm_nn<<<dim3(FFDIM/64, TTOK/64, 1), 256>>>(
            g_x, w_up + (long)i * DMODEL * FFDIM, g_ff2,
            TTOK, FFDIM, DMODEL, DMODEL, FFDIM, FFDIM, 0, 0, 0);

        gelu_mul_kernel<<<(TTOK * FFDIM + 255) / 256, 256>>>(g_ff1, g_ff2, TTOK * FFDIM);

        // ff = gu @ w_down[i]  (128 x 6912 @ 6912 x 1152)
        gemm_nn<<<dim3(DMODEL/64, TTOK/64, 1), 256>>>(
            g_ff1, w_down + (long)i * FFDIM * DMODEL, g_proj,
            TTOK, DMODEL, FFDIM, FFDIM, DMODEL, DMODEL, 0, 0, 0);

        // h += rms(ff, post_ff_norm_w)
        add_rms_kernel<<<TTOK, 256>>>(g_h, g_proj, post_ff_w + (long)i * DMODEL, DMODEL);
    }

    // logits = rms(h, final_norm_w) @ w_lm   (128 x 1152 @ 1152 x 32768)
    rms_kernel<<<TTOK, 256>>>(g_h, final_w, g_x, DMODEL);
    gemm_nn<<<dim3(VOCAB/64, TTOK/64, 1), 256>>>(
        g_x, w_lm, logits,
        TTOK, VOCAB, DMODEL, DMODEL, VOCAB, VOCAB, 0, 0, 0);
}

// round 3
// speedup vs baseline: 3.2252x; 3.2252x over previous
#include <cuda_runtime.h>
#include <math.h>

// ---------------------------------------------------------------------------
// Gemma3 prefill forward — Round 3: f32x2 packed-FMA GEMMs + split-K
// (Round-2 design resubmitted after infra failure; + fused GELU reduce)
// ---------------------------------------------------------------------------

#define LAY    12
#define DMODEL 1152
#define NHEAD  4
#define HDIM   256
#define FFDIM  6912
#define VOCAB  32768
#define TTOK   128
#define CCTX   1920
#define STOT   2048
#define QKVW   1536   // (NH+2)*HD

// ---- scratch (single device global, no allocations) ----
#define OFF_H     0
#define OFF_X     (OFF_H + TTOK*DMODEL)
#define OFF_QKV   (OFF_X + TTOK*DMODEL)
#define OFF_Q     (OFF_QKV + TTOK*QKVW)
#define OFF_K     (OFF_Q + NHEAD*TTOK*HDIM)
#define OFF_V     (OFF_K + STOT*HDIM)
#define OFF_SC    (OFF_V + HDIM*STOT)
#define OFF_ATT   (OFF_SC + NHEAD*TTOK*STOT)
#define OFF_PROJ  (OFF_ATT + TTOK*NHEAD*HDIM)
#define OFF_FF1   (OFF_PROJ + TTOK*DMODEL)
#define OFF_FF2   (OFF_FF1 + TTOK*FFDIM)
#define OFF_PART  (OFF_FF2 + TTOK*FFDIM)
#define PART_MAX  (2*TTOK*FFDIM)              // largest: gate/up split-2 partials
#define SCRATCH_TOTAL (OFF_PART + PART_MAX)

__device__ float g_scratch[SCRATCH_TOTAL];

// ---------------------------------------------------------------------------
// f32x2 helpers (packed-pair FMA; ptxas will not auto-fuse, must use PTX)
// ---------------------------------------------------------------------------
__device__ __forceinline__ unsigned long long pk2(float x) {
    unsigned long long r;
    asm("mov.b64 %0, {%1, %1};" : "=l"(r) : "f"(x));
    return r;
}
__device__ __forceinline__ void fma2(unsigned long long& d,
                                     unsigned long long a, unsigned long long b) {
    asm("fma.rn.f32x2 %0, %1, %2, %3;" : "=l"(d) : "l"(a), "l"(b), "l"(d));
}
__device__ __forceinline__ void unpk(unsigned long long v, float& lo, float& hi) {
    asm("mov.b64 {%0, %1}, %2;" : "=f"(lo), "=f"(hi) : "l"(v));
}

// ---------------------------------------------------------------------------
// GEMM: C[M=128, N] = A[128,K] @ B  (BT=0: B is K x N row-major;
//                                    BT=1: B is N x K row-major, i.e. A@B^T)
// Tile: 128 x 64, 256 threads, per-thread 8(M) x 4(N), M packed in f32x2.
// grid = (N/64, split, batch). split>1 writes dense partials [batch][z][128][Nt].
// ---------------------------------------------------------------------------
template<bool BT>
__global__ __launch_bounds__(256) void gemm_f2(
    const float* __restrict__ A, const float* __restrict__ B, float* __restrict__ C,
    int K, int lda, int ldb, int ldc, int ktiles_split,
    long sA, long sB, long sC)
{
    __shared__ float As[16 * 128];
    __shared__ float Bs[16 * 64];

    const int tid = threadIdx.x;
    const int bz = blockIdx.z, z = blockIdx.y;
    const int bn = blockIdx.x * 64;

    const float* Abase = A + (long)bz * sA;
    const float* Bb    = B + (long)bz * sB;

    const int ktot = K >> 4;
    const int kb   = z * ktiles_split;
    const int nkt  = min(ktiles_split, ktot - kb);

    const float* Ap = Abase + kb * 16;
    const float* Bp;
    if (BT) Bp = Bb + (long)bn * ldb + kb * 16;
    else    Bp = Bb + (long)(kb * 16) * ldb + bn;

    const int arow = tid >> 1, acol = (tid & 1) * 8;

    float4 pa0, pa1, pb0;
    {
        const float* ap = Ap + (long)arow * lda + acol;
        pa0 = *(const float4*)ap; pa1 = *(const float4*)(ap + 4);
        if (BT) { int n = tid >> 2, kc = (tid & 3) * 4;
                  pb0 = *(const float4*)(Bp + (long)n * ldb + kc); }
        else    { int r = tid >> 4, c = (tid & 15) * 4;
                  pb0 = *(const float4*)(Bp + (long)r * ldb + c); }
    }

    unsigned long long acc[16];
#pragma unroll
    for (int i = 0; i < 16; i++) acc[i] = 0ull;

    const int ty = tid >> 4, tx = tid & 15;
    const int ty8 = ty * 8, tx4 = tx * 4;

    for (int kt = 0; kt < nkt; kt++) {
        // commit prefetched tile to smem
#pragma unroll
        for (int j = 0; j < 4; j++) As[(acol + j) * 128 + arow]     = ((float*)&pa0)[j];
#pragma unroll
        for (int j = 0; j < 4; j++) As[(acol + 4 + j) * 128 + arow] = ((float*)&pa1)[j];
        if (BT) {
            int n = tid >> 2, kc = (tid & 3) * 4;
#pragma unroll
            for (int j = 0; j < 4; j++) Bs[(kc + j) * 64 + n] = ((float*)&pb0)[j];
        } else {
            int r = tid >> 4, c = (tid & 15) * 4;
            *(float4*)&Bs[r * 64 + c] = pb0;
        }
        __syncthreads();

        // prefetch next tile
        if (kt + 1 < nkt) {
            const float* ap = Ap + (long)arow * lda + (kt + 1) * 16 + acol;
            pa0 = *(const float4*)ap; pa1 = *(const float4*)(ap + 4);
            if (BT) { int n = tid >> 2, kc = (tid & 3) * 4;
                      pb0 = *(const float4*)(Bp + (long)n * ldb + (kt + 1) * 16 + kc); }
            else    { int r = tid >> 4, c = (tid & 15) * 4;
                      pb0 = *(const float4*)(Bp + (long)((kt + 1) * 16 + r) * ldb + c); }
        }

#pragma unroll
        for (int kk = 0; kk < 16; kk++) {
            const float* as = &As[kk * 128 + ty8];
            unsigned long long a0 = *(const unsigned long long*)(as);
            unsigned long long a1 = *(const unsigned long long*)(as + 2);
            unsigned long long a2 = *(const unsigned long long*)(as + 4);
            unsigned long long a3 = *(const unsigned long long*)(as + 6);
            float4 b = *(const float4*)&Bs[kk * 64 + tx4];
            unsigned long long b0 = pk2(b.x), b1 = pk2(b.y),
                               b2 = pk2(b.z), b3 = pk2(b.w);
            fma2(acc[0],  a0, b0); fma2(acc[1],  a0, b1);
            fma2(acc[2],  a0, b2); fma2(acc[3],  a0, b3);
            fma2(acc[4],  a1, b0); fma2(acc[5],  a1, b1);
            fma2(acc[6],  a1, b2); fma2(acc[7],  a1, b3);
            fma2(acc[8],  a2, b0); fma2(acc[9],  a2, b1);
            fma2(acc[10], a2, b2); fma2(acc[11], a2, b3);
            fma2(acc[12], a3, b0); fma2(acc[13], a3, b1);
            fma2(acc[14], a3, b2); fma2(acc[15], a3, b3);
        }
        __syncthreads();
    }

    const int Nt = gridDim.x * 64;
    const bool direct = (gridDim.y == 1);
#pragma unroll
    for (int mi = 0; mi < 4; mi++) {
        float lo[4], hi[4];
#pragma unroll
        for (int n = 0; n < 4; n++) unpk(acc[mi * 4 + n], lo[n], hi[n]);
        int m0 = ty8 + mi * 2;
        if (direct) {
            float* c0 = C + (long)bz * sC + (long)m0 * ldc + bn + tx4;
            *(float4*)c0         = make_float4(lo[0], lo[1], lo[2], lo[3]);
            *(float4*)(c0 + ldc) = make_float4(hi[0], hi[1], hi[2], hi[3]);
        } else {
            float* c0 = C + ((long)(bz * gridDim.y + z) * 128 + m0) * Nt + bn + tx4;
            *(float4*)c0        = make_float4(lo[0], lo[1], lo[2], lo[3]);
            *(float4*)(c0 + Nt) = make_float4(hi[0], hi[1], hi[2], hi[3]);
        }
    }
}

// Sum split-K partials: C[m*ldc + bz*Npart + n] = sum_s P[bz][s][m][n]
__global__ __launch_bounds__(256) void reduce_split(
    const float* __restrict__ P, float* __restrict__ C,
    int split, int Npart, int ldc)
{
    int bz = blockIdx.y;
    long idx = ((long)blockIdx.x * 256 + threadIdx.x) * 4;
    int m = (int)(idx / Npart);
    int n = (int)(idx % Npart);
    const float* base = P + (long)bz * split * TTOK * Npart + (long)m * Npart + n;
    float4 s = *(const float4*)base;
    for (int t = 1; t < split; t++) {
        float4 v = *(const float4*)(base + (long)t * TTOK * Npart);
        s.x += v.x; s.y += v.y; s.z += v.z; s.w += v.w;
    }
    *(float4*)(C + (long)m * ldc + bz * Npart + n) = s;
}

__device__ __forceinline__ float gelu_t(float x) {
    float x3 = x * x * x;
    return 0.5f * x * (1.f + tanhf(0.7978845608028654f * (x + 0.044715f * x3)));
}

// Reduce "up" partials, then out = gelu(gate) * up  (gate already reduced in G)
__global__ __launch_bounds__(256) void reduce_split_gelu(
    const float* __restrict__ P, const float* __restrict__ G,
    float* __restrict__ C, int split, int Npart)
{
    long idx = ((long)blockIdx.x * 256 + threadIdx.x) * 4;
    const float* base = P + idx;
    float4 s = *(const float4*)base;
    for (int t = 1; t < split; t++) {
        float4 v = *(const float4*)(base + (long)t * TTOK * Npart);
        s.x += v.x; s.y += v.y; s.z += v.z; s.w += v.w;
    }
    float4 g = *(const float4*)(G + idx);
    s.x *= gelu_t(g.x); s.y *= gelu_t(g.y);
    s.z *= gelu_t(g.z); s.w *= gelu_t(g.w);
    *(float4*)(C + idx) = s;
}

// ---------------------------------------------------------------------------
// RMSNorm kernels
// ---------------------------------------------------------------------------
__global__ __launch_bounds__(256) void rms_kernel(
    const float* __restrict__ x, const float* __restrict__ w,
    float* __restrict__ y, int ncols)
{
    int row = blockIdx.x;
    const float* xr = x + (long)row * ncols;
    __shared__ float red[256];
    int tid = threadIdx.x;
    float ss = 0.f;
    for (int c = tid; c < ncols; c += 256) { float v = xr[c]; ss += v * v; }
    red[tid] = ss; __syncthreads();
    for (int s = 128; s > 0; s >>= 1) { if (tid < s) red[tid] += red[tid + s]; __syncthreads(); }
    float inv = rsqrtf(red[0] / ncols + 1e-6f);
    for (int c = tid; c < ncols; c += 256)
        y[(long)row * ncols + c] = xr[c] * inv * (1.f + w[c]);
}

__global__ __launch_bounds__(256) void add_rms_kernel(
    float* __restrict__ h, const float* __restrict__ p,
    const float* __restrict__ w, int ncols)
{
    int row = blockIdx.x;
    const float* pr = p + (long)row * ncols;
    __shared__ float red[256];
    int tid = threadIdx.x;
    float ss = 0.f;
    for (int c = tid; c < ncols; c += 256) { float v = pr[c]; ss += v * v; }
    red[tid] = ss; __syncthreads();
    for (int s = 128; s > 0; s >>= 1) { if (tid < s) red[tid] += red[tid + s]; __syncthreads(); }
    float inv = rsqrtf(red[0] / ncols + 1e-6f);
    for (int c = tid; c < ncols; c += 256)
        h[(long)row * ncols + c] += pr[c] * inv * (1.f + w[c]);
}

// ---------------------------------------------------------------------------
// Q/K rmsnorm + RoPE + V scatter (one block per token, 256 threads = HD)
// ---------------------------------------------------------------------------
__global__ __launch_bounds__(256) void qk_rope_kernel(
    const float* __restrict__ qkv,
    const float* __restrict__ qw, const float* __restrict__ kw,
    const float* __restrict__ cosp, const float* __restrict__ sinp,
    float* __restrict__ qout, float* __restrict__ Kfull, float* __restrict__ Vfull,
    float* __restrict__ kslice, float* __restrict__ vslice)
{
    int t = blockIdx.x;
    int d = threadIdx.x;
    __shared__ float red[256];
    __shared__ float buf[256];

    float cosv = cosp[t * HDIM + d];
    float sinv = sinp[t * HDIM + d];

    for (int hidx = 0; hidx < 5; hidx++) {
        float v = qkv[(long)t * QKVW + hidx * HDIM + d];
        red[d] = v * v; __syncthreads();
        for (int s = 128; s > 0; s >>= 1) { if (d < s) red[d] += red[d + s]; __syncthreads(); }
        float inv = rsqrtf(red[0] / HDIM + 1e-6f);
        const float* w = (hidx < 4) ? qw : kw;
        float xn = v * inv * (1.f + w[d]);
        buf[d] = xn; __syncthreads();
        float rot = (d < 128) ? -buf[d + 128] : buf[d - 128];
        float r = xn * cosv + rot * sinv;
        if (hidx < 4) {
            qout[(long)hidx * TTOK * HDIM + (long)t * HDIM + d] = r;
        } else {
            Kfull[(long)(CCTX + t) * HDIM + d] = r;
            kslice[(long)t * HDIM + d] = r;
        }
        __syncthreads();
    }
    float vv = qkv[(long)t * QKVW + 5 * HDIM + d];
    Vfull[(long)d * STOT + CCTX + t] = vv;
    vslice[(long)d * TTOK + t] = vv;
}

__global__ __launch_bounds__(256) void copy_v_kernel(
    const float* __restrict__ src, float* __restrict__ Vfull)
{
    int idx = blockIdx.x * 256 + threadIdx.x;
    if (idx < HDIM * CCTX) {
        int d = idx / CCTX, s = idx % CCTX;
        Vfull[(long)d * STOT + s] = src[idx];
    }
}

// ---------------------------------------------------------------------------
// softmax with tanh soft-cap + mask
// ---------------------------------------------------------------------------
__global__ __launch_bounds__(256) void softmax_kernel(
    float* __restrict__ sc, const float* __restrict__ mask)
{
    int t = blockIdx.x, h = blockIdx.y;
    float* row = sc + ((long)h * TTOK + t) * STOT;
    const float* mrow = mask + (long)t * STOT;
    __shared__ float red[256];
    int tid = threadIdx.x;
    const float scale = 0.0625f;
    const float invcap = 1.f / 50.f;

    float vals[8];
    float vmax = -1e30f;
#pragma unroll
    for (int j = 0; j < 8; j++) {
        int s = tid + j * 256;
        float v = row[s] * scale;
        v = tanhf(v * invcap) * 50.f + mrow[s];
        vals[j] = v;
        vmax = fmaxf(vmax, v);
    }
    red[tid] = vmax; __syncthreads();
    for (int s = 128; s > 0; s >>= 1) { if (tid < s) red[tid] = fmaxf(red[tid], red[tid + s]); __syncthreads(); }
    float m = red[0]; __syncthreads();
    float lsum = 0.f;
#pragma unroll
    for (int j = 0; j < 8; j++) { vals[j] = expf(vals[j] - m); lsum += vals[j]; }
    red[tid] = lsum; __syncthreads();
    for (int s = 128; s > 0; s >>= 1) { if (tid < s) red[tid] += red[tid + s]; __syncthreads(); }
    float inv = 1.f / red[0];
#pragma unroll
    for (int j = 0; j < 8; j++) row[tid + j * 256] = vals[j] * inv;
}

// ---------------------------------------------------------------------------
// launch
// ---------------------------------------------------------------------------
extern "C" void kernel_launch(void* const* d_in, const int* in_sizes, int n_in,
                              void* d_out, int out_size)
{
    (void)in_sizes; (void)n_in; (void)out_size;
    const float* emb        = (const float*)d_in[0];
    const float* mask_g     = (const float*)d_in[1];
    const float* mask_l     = (const float*)d_in[2];
    const float* pe_cos     = (const float*)d_in[3];
    const float* pe_sin     = (const float*)d_in[4];
    const float* pe_cos_loc = (const float*)d_in[5];
    const float* pe_sin_loc = (const float*)d_in[6];
    const float* kv_k       = (const float*)d_in[7];
    const float* kv_v       = (const float*)d_in[8];
    const float* pre_attn_w = (const float*)d_in[9];
    const float* q_norm_w   = (const float*)d_in[10];
    const float* k_norm_w   = (const float*)d_in[11];
    const float* post_attn_w= (const float*)d_in[12];
    const float* pre_ff_w   = (const float*)d_in[13];
    const float* post_ff_w  = (const float*)d_in[14];
    const float* final_w    = (const float*)d_in[15];
    const float* w_qkv      = (const float*)d_in[16];
    const float* w_out      = (const float*)d_in[17];
    const float* w_gate     = (const float*)d_in[18];
    const float* w_up       = (const float*)d_in[19];
    const float* w_down     = (const float*)d_in[20];
    const float* w_lm       = (const float*)d_in[21];

    float* out    = (float*)d_out;
    float* logits = out;
    float* kout   = out + (long)TTOK * VOCAB;
    float* vout   = kout + (long)LAY * TTOK * HDIM;

    void* sp = nullptr;
    cudaGetSymbolAddress(&sp, g_scratch);
    float* S = (float*)sp;
    float* g_h    = S + OFF_H;
    float* g_x    = S + OFF_X;
    float* g_qkv  = S + OFF_QKV;
    float* g_q    = S + OFF_Q;
    float* g_K    = S + OFF_K;
    float* g_V    = S + OFF_V;
    float* g_sc   = S + OFF_SC;
    float* g_att  = S + OFF_ATT;
    float* g_proj = S + OFF_PROJ;
    float* g_ff1  = S + OFF_FF1;
    float* g_ff2  = S + OFF_FF2;
    float* g_part = S + OFF_PART;

    cudaMemcpyAsync(g_h, emb, (long)TTOK * DMODEL * sizeof(float),
                    cudaMemcpyDeviceToDevice);

    for (int i = 0; i < LAY; i++) {
        bool is_local = ((i + 1) % 6 == 0);
        const float* cosP = is_local ? pe_cos_loc : pe_cos;
        const float* sinP = is_local ? pe_sin_loc : pe_sin;
        const float* mask = is_local ? mask_l : mask_g;

        // x = rms(h, pre_attn_norm_w)
        rms_kernel<<<TTOK, 256>>>(g_h, pre_attn_w + (long)i * DMODEL, g_x, DMODEL);

        // qkv = x @ w_qkv[i] : 128x1536, K=1152, split 6
        gemm_f2<false><<<dim3(QKVW / 64, 6, 1), 256>>>(
            g_x, w_qkv + (long)i * DMODEL * QKVW, g_part,
            DMODEL, DMODEL, QKVW, 0, 12, 0, 0, 0);
        reduce_split<<<dim3(TTOK * QKVW / 1024, 1), 256>>>(g_part, g_qkv, 6, QKVW, QKVW);

        cudaMemcpyAsync(g_K, kv_k + (long)i * CCTX * HDIM,
                        (long)CCTX * HDIM * sizeof(float), cudaMemcpyDeviceToDevice);
        copy_v_kernel<<<(HDIM * CCTX + 255) / 256, 256>>>(
            kv_v + (long)i * HDIM * CCTX, g_V);

        qk_rope_kernel<<<TTOK, 256>>>(
            g_qkv, q_norm_w + (long)i * HDIM, k_norm_w + (long)i * HDIM,
            cosP, sinP, g_q, g_K, g_V,
            kout + (long)i * TTOK * HDIM, vout + (long)i * HDIM * TTOK);

        // scores[h] = q[h] @ K^T : N=2048, K=256, batch 4, no split
        gemm_f2<true><<<dim3(STOT / 64, 1, NHEAD), 256>>>(
            g_q, g_K, g_sc,
            HDIM, HDIM, HDIM, STOT, 16,
            (long)TTOK * HDIM, 0, (long)TTOK * STOT);

        softmax_kernel<<<dim3(TTOK, NHEAD), 256>>>(g_sc, mask);

        // att[h] = attn[h] @ V^T : N=256, K=2048, batch 4, split 8
        gemm_f2<true><<<dim3(HDIM / 64, 8, NHEAD), 256>>>(
            g_sc, g_V, g_part,
            STOT, STOT, STOT, 0, 16,
            (long)TTOK * STOT, 0, 0);
        reduce_split<<<dim3(TTOK * HDIM / 1024, NHEAD), 256>>>(
            g_part, g_att, 8, HDIM, NHEAD * HDIM);

        // proj = att @ w_out[i] : N=1152, K=1024, split 8
        gemm_f2<false><<<dim3(DMODEL / 64, 8, 1), 256>>>(
            g_att, w_out + (long)i * (NHEAD * HDIM) * DMODEL, g_part,
            NHEAD * HDIM, NHEAD * HDIM, DMODEL, 0, 8, 0, 0, 0);
        reduce_split<<<dim3(TTOK * DMODEL / 1024, 1), 256>>>(g_part, g_proj, 8, DMODEL, DMODEL);

        add_rms_kernel<<<TTOK, 256>>>(g_h, g_proj, post_attn_w + (long)i * DMODEL, DMODEL);

        rms_kernel<<<TTOK, 256>>>(g_h, pre_ff_w + (long)i * DMODEL, g_x, DMODEL);

        // gate : N=6912, K=1152, split 2
        gemm_f2<false><<<dim3(FFDIM / 64, 2, 1), 256>>>(
            g_x, w_gate + (long)i * DMODEL * FFDIM, g_part,
            DMODEL, DMODEL, FFDIM, 0, 36, 0, 0, 0);
        reduce_split<<<dim3(TTOK * FFDIM / 1024, 1), 256>>>(g_part, g_ff2, 2, FFDIM, FFDIM);

        // up : N=6912, K=1152, split 2 ; then ff1 = gelu(gate) * up (fused)
        gemm_f2<false><<<dim3(FFDIM / 64, 2, 1), 256>>>(
            g_x, w_up + (long)i * DMODEL * FFDIM, g_part,
            DMODEL, DMODEL, FFDIM, 0, 36, 0, 0, 0);
        reduce_split_gelu<<<dim3(TTOK * FFDIM / 1024, 1), 256>>>(
            g_part, g_ff2, g_ff1, 2, FFDIM);

        // down : N=1152, K=6912, split 8
        gemm_f2<false><<<dim3(DMODEL / 64, 8, 1), 256>>>(
            g_ff1, w_down + (long)i * FFDIM * DMODEL, g_part,
            FFDIM, FFDIM, DMODEL, 0, 54, 0, 0, 0);
        reduce_split<<<dim3(TTOK * DMODEL / 1024, 1), 256>>>(g_part, g_proj, 8, DMODEL, DMODEL);

        add_rms_kernel<<<TTOK, 256>>>(g_h, g_proj, post_ff_w + (long)i * DMODEL, DMODEL);
    }

    rms_kernel<<<TTOK, 256>>>(g_h, final_w, g_x, DMODEL);
    // lm head : N=32768, K=1152, no split (512 CTAs)
    gemm_f2<false><<<dim3(VOCAB / 64, 1, 1), 256>>>(
        g_x, w_lm, logits,
        DMODEL, DMODEL, VOCAB, VOCAB, 72, 0, 0, 0);
}